// round 11
// baseline (speedup 1.0000x reference)
#include <cuda_runtime.h>
#include <math.h>

#define FULLMASK 0xffffffffu
#define NS   25
#define NF   216
#define TLEN 2048
#define NTRIP 682          // triples covering t = 2 .. 2047

// dynamic smem layout (bytes). Q tables packed at stride 25 float4 per flat.
#define OFF_B     0                         // 216*32*4          = 27648
#define OFF_Q2    27648                     // 216*25*16 + pad   = 86528
#define OFF_Q1    (27648 + 86528)           // 86528  (sFlat aliases here)
#define OFF_TRIP  (OFF_Q1 + 86528)          // 4*684*8           = 21888
#define OFF_A     (OFF_TRIP + 21888)        // 2500
#define OFF_I     (OFF_A + 2500)            // 128
#define OFF_RED   (OFF_I + 128)             // 512
#define SMEM_TOTAL (OFF_RED + 512)          // 225732

// ---------------- constant tables ----------------
__constant__ __align__(16) int c_srcTab[32 * 4] = {
    0,0,0,0,     0,1,1,1,     1,2,2,2,     2,3,3,3,
    3,16,4,4,    4,5,5,5,     5,6,6,6,     6,19,3,7,
    7,8,8,8,     8,9,9,9,     9,22,3,6,    10,11,11,11,
    11,12,12,12, 12,13,13,13, 3,16,14,14,  14,15,15,15,
    15,16,16,16, 6,19,17,17,  17,18,18,18, 18,19,19,19,
    9,22,20,20,  20,21,21,21, 21,22,22,22, 13,23,23,23,
    23,24,24,24, 25,25,25,25, 26,26,26,26, 27,27,27,27,
    28,28,28,28, 29,29,29,29, 30,30,30,30, 31,31,31,31
};
__constant__ int c_deg[32] = {1,1,1,1,2,1,1,3,1,1,4,1,1,2,2,1,1,2,1,1,2,1,1,2,2,0,0,0,0,0,0,0};

__constant__ int c_pred[25][4] = {
    {0,0,0,0},{0,0,0,0},{1,0,0,0},{2,0,0,0},{3,16,0,0},{4,0,0,0},{5,0,0,0},
    {6,19,3,0},{7,0,0,0},{8,0,0,0},{9,22,3,6},{10,0,0,0},{11,0,0,0},{12,13,0,0},
    {3,16,0,0},{14,0,0,0},{15,0,0,0},{6,19,0,0},{17,0,0,0},{18,0,0,0},
    {9,22,0,0},{20,0,0,0},{21,0,0,0},{13,23,0,0},{23,24,0,0}
};
__constant__ int c_pcnt[25] = {1,1,1,1,2,1,1,3,1,1,4,1,1,2,2,1,1,2,1,1,2,1,1,2,2};

__constant__ int c_adds[29][7] = {
    { 0, 10,10,10, 0,1,    0},
    { 1, 10,10, 0, 0,1,   84},
    { 2, 10, 0, 3, 0,1,  105},
    { 3,  0, 3, 2, 0,0,    0},
    { 4,  3, 2,10, 0,1,  111},
    { 5,  2,10,10, 0,1,  123},
    { 6, 10,10,10, 0,1,  159},
    { 7, 10,10,10, 0,1,  243},
    { 8, 10,10,10, 0,1,  327},
    { 9, 10,10,10, 0,1,  411},
    {10, 10,10, 3, 2,1,  495},
    {11, 10, 3, 0, 2,1,  511},
    {11, 10, 3, 2, 2,1,  515},
    {12,  3, 0, 0, 2,0,    0},
    {12,  3, 0, 2, 2,0,    0},
    {12,  3, 2, 0, 2,0,    0},
    {13, 10,10,10, 2,1,  519},
    {14, 10,10,10, 0,1,  583},
    {15, 10,10,10, 0,1,  667},
    {16, 10,10,10, 0,1,  751},
    {17, 10,10,10, 0,1,  835},
    {18, 10,10,10, 0,1,  919},
    {19, 10,10,10, 0,1, 1003},
    {20, 10,10,10, 0,1, 1087},
    {21, 10,10,10, 0,1, 1171},
    {22, 10,10,10, 0,1, 1255},
    {23, 10,10, 5, 2,1, 1339},
    {23, 10, 5, 5, 2,1, 1355},
    {24,  5, 5, 5, 2,0,    0}
};

// ---------------- helpers ----------------
__device__ __forceinline__ int codeList(int ch, int* o) {
    if (ch == 10) { o[0]=0; o[1]=1; o[2]=2; o[3]=3; return 4; }
    o[0] = ch; return 1;
}

__device__ void addB(float* shB, const float* w,
                     int state, int e0, int e1, int e2,
                     int xp, int trainable, int k)
{
    int a0[6], a1[6], a2[6];
    int n0 = codeList(e0, a0);
    int n1 = codeList(e1, a1);
    int n2 = codeList(e2, a2);
    if (xp == 0) { a0[n0++] = 4; a1[n1++] = 4; }
    int t = 0;
    for (int i0 = 0; i0 < n0; i0++) { int c0 = a0[i0];
        for (int i1 = 0; i1 < n1; i1++) { int c1 = a1[i1];
            if (c0 != 4 && c1 == 4) continue;
            for (int i2 = 0; i2 < n2; i2++) { int c2 = a2[i2];
                shB[((c0*36 + c1*6 + c2) << 5) + state] = trainable ? w[k + t] : 1.0f;
                t++;
            }
        }
    }
}

// ---------------- fused kernel: 3 steps/iter, dual vectorized tables ----------------
__global__ __launch_bounds__(128, 1)
void hmm_fused(const float* __restrict__ tw,
               const float* __restrict__ ew,
               const float* __restrict__ iw,
               const int* __restrict__ tokens,
               float* __restrict__ out, int rows)
{
    extern __shared__ char dyn[];
    float*  shB   = (float*) (dyn + OFF_B);     // [flat][state(32)]
    float4* sQ2   = (float4*)(dyn + OFF_Q2);    // [f*25+lane]: C_p*B[K2_p][f]
    float4* sQ1   = (float4*)(dyn + OFF_Q1);    // [f*25+lane]: B[K1_p][f]
    short*  sFlat = (short*) (dyn + OFF_Q1);    // ALIAS: flats live here pre-Q1
    short4* sTrip = (short4*)(dyn + OFF_TRIP);  // 4 rows x 684 packed triples
    float*  sA    = (float*) (dyn + OFF_A);
    float*  sI    = (float*) (dyn + OFF_I);
    float*  sRed  = (float*) (dyn + OFF_RED);
    const int tid = threadIdx.x;

    // ---- init ----
    for (int i = tid; i < NF*32; i += 128) shB[i] = ((i & 31) < 25) ? -1e30f : 0.0f;
    for (int i = tid; i < 25*25;  i += 128) sA[i] = -1e30f;
    __syncthreads();

    // ---- B logits ----
    if (tid < 29) {
        const int* d = c_adds[tid];
        addB(shB, ew, d[0], d[1], d[2], d[3], d[4], d[5], d[6]);
    }
    // ---- A logits ----
    if (tid == 32) {
        float w0=tw[0],w1=tw[1],w2=tw[2],w3=tw[3],w4=tw[4];
        float w5=tw[5],w6=tw[6],w7=tw[7],w8=tw[8],w9=tw[9];
        sA[0*25+0]=1.f-w0; sA[0*25+1]=w0;
        sA[1*25+2]=1.f;    sA[2*25+3]=1.f;
        sA[3*25+4]=w1;     sA[6*25+7]=w2;
        sA[4*25+5]=1.f;    sA[7*25+8]=1.f;
        sA[5*25+6]=1.f;    sA[8*25+9]=1.f;
        sA[3*25+14]=w3;    sA[6*25+17]=w4;   sA[9*25+20]=w5;
        sA[9*25+10]=1.f-w5;
        sA[14*25+15]=1.f;  sA[17*25+18]=1.f; sA[20*25+21]=1.f;
        sA[15*25+16]=1.f;  sA[18*25+19]=1.f; sA[21*25+22]=1.f;
        sA[16*25+4]=w6;    sA[19*25+7]=w7;   sA[22*25+10]=w8;
        sA[16*25+14]=1.f-w6; sA[19*25+17]=1.f-w7; sA[22*25+20]=1.f-w8;
        sA[3*25+7]=1.f - w9*w9;
        sA[3*25+10]=1.f - w9*w9*w9;
        sA[6*25+10]=1.f - w9*w9;
        sA[10*25+11]=1.f; sA[11*25+12]=1.f; sA[12*25+13]=1.f;
        sA[13*25+13]=1.f; sA[13*25+23]=1.f;
        sA[23*25+23]=1.f; sA[23*25+24]=1.f; sA[24*25+24]=1.f;
    }
    // ---- I softmax ----
    if (tid == 64) {
        float mx = -1e30f;
        for (int i = 0; i < 9; i++) mx = fmaxf(mx, iw[i]);
        float v[9], sum = 0.f;
        for (int i = 0; i < 9; i++) { v[i] = expf(iw[i]-mx); sum += v[i]; }
        for (int i = 0; i < 9; i++) sI[i] = v[i] / sum;
        for (int i = 9; i < 32; i++) sI[i] = 0.f;
    }

    // ---- per-warp: flat contexts (alias region) + packed triples ----
    const int lane = tid & 31;
    const int wq   = tid >> 5;
    const int row  = blockIdx.x * 4 + wq;
    short*  myFlat = sFlat + wq * TLEN;
    short4* myTrip = sTrip + wq * 684;
    const int* tok = tokens + (size_t)row * TLEN;
    int flat0 = 168, flat1 = 144;
    if (row < rows) {
        int c1 = 4, c2 = 4;
        for (int t0 = 0; t0 < TLEN; t0 += 32) {
            int tcv = tok[t0 + lane];
            int t1v = __shfl_up_sync(FULLMASK, tcv, 1);
            int t2v = __shfl_up_sync(FULLMASK, tcv, 2);
            if (lane == 0) { t1v = c1; t2v = c2; }
            if (lane == 1) { t2v = c1; }
            myFlat[t0 + lane] = (short)(t2v*36 + t1v*6 + tcv);
            c2 = __shfl_sync(FULLMASK, tcv, 30);
            c1 = __shfl_sync(FULLMASK, tcv, 31);
        }
        __syncwarp();
        for (int i = lane; i < NTRIP; i += 32) {
            int b = 2 + 3*i;
            myTrip[i] = make_short4(myFlat[b], myFlat[b+1], myFlat[b+2], 0);
        }
        flat0 = myFlat[0];     // save before Q1 overwrites the alias region
        flat1 = myFlat[1];
    }
    __syncthreads();

    // ---- A row softmax ----
    if (tid < 25) {
        float mx = -1e30f;
        for (int j = 0; j < 25; j++) mx = fmaxf(mx, sA[tid*25+j]);
        float s = 0.f;
        for (int j = 0; j < 25; j++) { float v = expf(sA[tid*25+j]-mx); sA[tid*25+j]=v; s+=v; }
        float inv = 1.f / s;
        for (int j = 0; j < 25; j++) sA[tid*25+j] *= inv;
    }
    // ---- B column softmax, 4-way parallel per state ----
    {
        const int s  = tid & 31;
        const int ch = tid >> 5;
        const int f0 = ch * 54, f1 = f0 + 54;
        float mx = -1e30f;
        for (int f = f0; f < f1; f++) mx = fmaxf(mx, shB[(f<<5)+s]);
        sRed[ch*32 + s] = mx;
        __syncthreads();
        mx = fmaxf(fmaxf(sRed[s], sRed[32+s]), fmaxf(sRed[64+s], sRed[96+s]));
        float sum = 0.f;
        for (int f = f0; f < f1; f++) {
            float v = __expf(shB[(f<<5)+s] - mx);
            shB[(f<<5)+s] = v; sum += v;
        }
        __syncthreads();
        sRed[ch*32 + s] = sum;
        __syncthreads();
        float tot = (sRed[s] + sRed[32+s]) + (sRed[64+s] + sRed[96+s]);
        float inv = 1.f / tot;
        for (int f = f0; f < f1; f++) shB[(f<<5)+s] *= inv;
    }
    __syncthreads();

    // ---- 3-step path table for lane j (<=4 paths; 23/24 intermediates pruned:
    //      B[23/24][f] = 0 on every reachable flat, so those paths are exactly 0) ----
    int   ps[4] = {0,0,0,0};
    int   j1[4] = {0,0,0,0};
    int   j2[4] = {0,0,0,0};
    float pcc[4] = {0.f,0.f,0.f,0.f};
    if (lane < 25) {
        int cnt = 0;
        for (int a2 = 0; a2 < c_pcnt[lane]; a2++) {
            int k2 = c_pred[lane][a2];
            if (k2 >= 23) continue;
            for (int a1 = 0; a1 < c_pcnt[k2]; a1++) {
                int k1 = c_pred[k2][a1];
                if (k1 >= 23) continue;
                for (int a0 = 0; a0 < c_pcnt[k1]; a0++) {
                    int s = c_pred[k1][a0];
                    ps[cnt] = s; j1[cnt] = k1; j2[cnt] = k2;
                    pcc[cnt] = sA[s*25+k1] * sA[k1*25+k2] * sA[k2*25+lane] * 8388608.0f; // 2^23
                    cnt++;
                }
            }
        }
    }
    const int S0 = ps[0], S1 = ps[1], S2 = ps[2], S3 = ps[3];

    // ---- build Q1/Q2 tables (stride-25 float4; lanes >=25 skip writes) ----
    {
        int ja0 = j1[0], ja1 = j1[1], ja2 = j1[2], ja3 = j1[3];
        int kb0 = j2[0], kb1 = j2[1], kb2 = j2[2], kb3 = j2[3];
        if (lane < 25) {
            for (int f = wq * 54; f < wq * 54 + 54; f++) {
                int fo = f << 5;
                float4 q1, q2;
                q1.x = shB[fo + ja0];
                q1.y = shB[fo + ja1];
                q1.z = shB[fo + ja2];
                q1.w = shB[fo + ja3];
                q2.x = pcc[0] * shB[fo + kb0];
                q2.y = pcc[1] * shB[fo + kb1];
                q2.z = pcc[2] * shB[fo + kb2];
                q2.w = pcc[3] * shB[fo + kb3];
                sQ1[f * 25 + lane] = q1;
                sQ2[f * 25 + lane] = q2;
            }
        }
    }
    __syncthreads();

    // 1-step table (t=1)
    const int u0 = c_srcTab[lane*4+0], u1 = c_srcTab[lane*4+1];
    const int u2 = c_srcTab[lane*4+2], u3 = c_srcTab[lane*4+3];
    const int dg = c_deg[lane];
    float v0 = (lane < 25 && dg > 0) ? sA[u0*25 + lane] : 0.f;
    float v1 = (lane < 25 && dg > 1) ? sA[u1*25 + lane] : 0.f;
    float v2 = (lane < 25 && dg > 2) ? sA[u2*25 + lane] : 0.f;
    float v3 = (lane < 25 && dg > 3) ? sA[u3*25 + lane] : 0.f;

    if (row >= rows) return;

    // ---- t = 0 ----
    float a = sI[lane] * shB[(flat0 << 5) + lane];

    // ---- t = 1: single 1-step ----
    {
        float e = shB[(flat1 << 5) + lane];
        float x0 = __shfl_sync(FULLMASK, a, u0);
        float x1 = __shfl_sync(FULLMASK, a, u1);
        float x2 = __shfl_sync(FULLMASK, a, u2);
        float x3 = __shfl_sync(FULLMASK, a, u3);
        a = (fmaf(x0, v0, x1*v1) + fmaf(x2, v2, x3*v3)) * e;
    }
    int expsum = 0;
    float sc = 1.f; int pend = 0;

    // ---- head: triples 0,1 (measure at 0, apply at 1) ----
#define TRIPM(I, MODE)                                                        \
    {                                                                         \
        short4 tf = myTrip[(I)];                                              \
        float4 q1 = sQ1[((int)tf.x) * 25 + lane];                             \
        float4 q2 = sQ2[((int)tf.y) * 25 + lane];                             \
        float e  = shB[(((int)tf.z) << 5) + lane];                            \
        float w0 = q1.x * q2.x * e;                                           \
        float w1 = q1.y * q2.y * e;                                           \
        float w2 = q1.z * q2.z * e;                                           \
        float w3 = q1.w * q2.w * e;                                           \
        float x0 = __shfl_sync(FULLMASK, a, S0);                              \
        float x1 = __shfl_sync(FULLMASK, a, S1);                              \
        float x2 = __shfl_sync(FULLMASK, a, S2);                              \
        float x3 = __shfl_sync(FULLMASK, a, S3);                              \
        a = fmaf(x1, w1, x0*w0) + fmaf(x3, w3, x2*w2);                        \
        if ((MODE) == 1) {                                                    \
            int m = __reduce_max_sync(FULLMASK, (__float_as_int(a) >> 23) & 255); \
            sc = __int_as_float((254 - m) << 23);                             \
            pend = m - 127;                                                   \
        }                                                                     \
        if ((MODE) == 2) { a *= sc; expsum += pend; }                         \
    }

    TRIPM(0, 1) TRIPM(1, 2)
#undef TRIPM

    // ---- main: 85 blocks of 8 triples (iters 2..681), trips via 4x LDS.128 ----
#define STAGE(i)                                                              \
    {                                                                         \
        float4 q1 = sQ1[F0[(i)] + lane];                                      \
        float4 q2 = sQ2[F1[(i)] + lane];                                      \
        float e  = shB[F2[(i)] + lane];                                       \
        W[(i)][0] = q1.x * q2.x * e;                                          \
        W[(i)][1] = q1.y * q2.y * e;                                          \
        W[(i)][2] = q1.z * q2.z * e;                                          \
        W[(i)][3] = q1.w * q2.w * e;                                          \
    }

    for (int ib = 2; ib <= 674; ib += 8) {
        // load 8 packed triples with 4 LDS.128 (ib even -> 16B aligned)
        const uint4* tp = (const uint4*)(myTrip + ib);
        uint4 T0 = tp[0], T1 = tp[1], T2 = tp[2], T3 = tp[3];
        int F0[8], F1[8], F2[8];
        F0[0]=(int)(T0.x&0xffffu)*25; F1[0]=(int)(T0.x>>16)*25; F2[0]=(int)(T0.y&0xffffu)<<5;
        F0[1]=(int)(T0.z&0xffffu)*25; F1[1]=(int)(T0.z>>16)*25; F2[1]=(int)(T0.w&0xffffu)<<5;
        F0[2]=(int)(T1.x&0xffffu)*25; F1[2]=(int)(T1.x>>16)*25; F2[2]=(int)(T1.y&0xffffu)<<5;
        F0[3]=(int)(T1.z&0xffffu)*25; F1[3]=(int)(T1.z>>16)*25; F2[3]=(int)(T1.w&0xffffu)<<5;
        F0[4]=(int)(T2.x&0xffffu)*25; F1[4]=(int)(T2.x>>16)*25; F2[4]=(int)(T2.y&0xffffu)<<5;
        F0[5]=(int)(T2.z&0xffffu)*25; F1[5]=(int)(T2.z>>16)*25; F2[5]=(int)(T2.w&0xffffu)<<5;
        F0[6]=(int)(T3.x&0xffffu)*25; F1[6]=(int)(T3.x>>16)*25; F2[6]=(int)(T3.y&0xffffu)<<5;
        F0[7]=(int)(T3.z&0xffffu)*25; F1[7]=(int)(T3.z>>16)*25; F2[7]=(int)(T3.w&0xffffu)<<5;

        float W[8][4];
        STAGE(0) STAGE(1)
        #pragma unroll
        for (int i = 0; i < 8; i++) {
            if (i < 6) STAGE(i+2)
            float x0 = __shfl_sync(FULLMASK, a, S0);
            float x1 = __shfl_sync(FULLMASK, a, S1);
            float x2 = __shfl_sync(FULLMASK, a, S2);
            float x3 = __shfl_sync(FULLMASK, a, S3);
            a = fmaf(x1, W[i][1], x0*W[i][0]) + fmaf(x3, W[i][3], x2*W[i][2]);
            if (i == 5) {
                int m = __reduce_max_sync(FULLMASK, (__float_as_int(a) >> 23) & 255);
                sc = __int_as_float((254 - m) << 23);
                pend = m - 127;
            }
            if (i == 7) { a *= sc; expsum += pend; }
        }
    }
#undef STAGE

    // ---- final: ll = log(sum alpha) + (expsum - 23*682) * ln2 ----
    float s = a;
    #pragma unroll
    for (int o = 16; o; o >>= 1) s += __shfl_xor_sync(FULLMASK, s, o);
    if (lane == 0)
        out[row] = logf(s) + 0.6931471805599453f * (float)(expsum - 15686);
}

// ---------------- entry point ----------------
extern "C" void kernel_launch(void* const* d_in, const int* in_sizes, int n_in,
                              void* d_out, int out_size)
{
    const float* tw     = (const float*)d_in[0];
    const float* ew     = (const float*)d_in[1];
    const float* iw     = (const float*)d_in[2];
    const int*   tokens = (const int*)  d_in[3];
    float*       out    = (float*)d_out;

    int rows = in_sizes[3] / TLEN;

    cudaFuncSetAttribute(hmm_fused,
                         cudaFuncAttributeMaxDynamicSharedMemorySize,
                         SMEM_TOTAL);
    hmm_fused<<<(rows + 3) / 4, 128, SMEM_TOTAL>>>(tw, ew, iw, tokens, out, rows);
}

// round 12
// speedup vs baseline: 1.5518x; 1.5518x over previous
#include <cuda_runtime.h>
#include <math.h>

#define FULLMASK 0xffffffffu
#define NS   25
#define NF   216
#define TLEN 2048
#define NTRIP 682          // triples covering t = 2 .. 2047

// dynamic smem layout (bytes)
#define OFF_B     0                          // 216*32*4 = 27648
#define OFF_Q2    27648                      // 216*32*16 = 110592 (float4, stride 32)
#define OFF_Q1B   (27648 + 110592)           // 216*32*8  = 55296  (bf16x4, stride 32)
                                             //   sFlat (4*2048*2 = 16384) ALIASES here
#define OFF_TRIP  (OFF_Q1B + 55296)          // 4*684*8 = 21888
#define OFF_A     (OFF_TRIP + 21888)         // 2500
#define OFF_I     (OFF_A + 2500)             // 128
#define OFF_RED   (OFF_I + 128)              // 512
#define SMEM_TOTAL (OFF_RED + 512)           // 218564

// ---------------- constant tables ----------------
__constant__ __align__(16) int c_srcTab[32 * 4] = {
    0,0,0,0,     0,1,1,1,     1,2,2,2,     2,3,3,3,
    3,16,4,4,    4,5,5,5,     5,6,6,6,     6,19,3,7,
    7,8,8,8,     8,9,9,9,     9,22,3,6,    10,11,11,11,
    11,12,12,12, 12,13,13,13, 3,16,14,14,  14,15,15,15,
    15,16,16,16, 6,19,17,17,  17,18,18,18, 18,19,19,19,
    9,22,20,20,  20,21,21,21, 21,22,22,22, 13,23,23,23,
    23,24,24,24, 25,25,25,25, 26,26,26,26, 27,27,27,27,
    28,28,28,28, 29,29,29,29, 30,30,30,30, 31,31,31,31
};
__constant__ int c_deg[32] = {1,1,1,1,2,1,1,3,1,1,4,1,1,2,2,1,1,2,1,1,2,1,1,2,2,0,0,0,0,0,0,0};

__constant__ int c_pred[25][4] = {
    {0,0,0,0},{0,0,0,0},{1,0,0,0},{2,0,0,0},{3,16,0,0},{4,0,0,0},{5,0,0,0},
    {6,19,3,0},{7,0,0,0},{8,0,0,0},{9,22,3,6},{10,0,0,0},{11,0,0,0},{12,13,0,0},
    {3,16,0,0},{14,0,0,0},{15,0,0,0},{6,19,0,0},{17,0,0,0},{18,0,0,0},
    {9,22,0,0},{20,0,0,0},{21,0,0,0},{13,23,0,0},{23,24,0,0}
};
__constant__ int c_pcnt[25] = {1,1,1,1,2,1,1,3,1,1,4,1,1,2,2,1,1,2,1,1,2,1,1,2,2};

__constant__ int c_adds[29][7] = {
    { 0, 10,10,10, 0,1,    0},
    { 1, 10,10, 0, 0,1,   84},
    { 2, 10, 0, 3, 0,1,  105},
    { 3,  0, 3, 2, 0,0,    0},
    { 4,  3, 2,10, 0,1,  111},
    { 5,  2,10,10, 0,1,  123},
    { 6, 10,10,10, 0,1,  159},
    { 7, 10,10,10, 0,1,  243},
    { 8, 10,10,10, 0,1,  327},
    { 9, 10,10,10, 0,1,  411},
    {10, 10,10, 3, 2,1,  495},
    {11, 10, 3, 0, 2,1,  511},
    {11, 10, 3, 2, 2,1,  515},
    {12,  3, 0, 0, 2,0,    0},
    {12,  3, 0, 2, 2,0,    0},
    {12,  3, 2, 0, 2,0,    0},
    {13, 10,10,10, 2,1,  519},
    {14, 10,10,10, 0,1,  583},
    {15, 10,10,10, 0,1,  667},
    {16, 10,10,10, 0,1,  751},
    {17, 10,10,10, 0,1,  835},
    {18, 10,10,10, 0,1,  919},
    {19, 10,10,10, 0,1, 1003},
    {20, 10,10,10, 0,1, 1087},
    {21, 10,10,10, 0,1, 1171},
    {22, 10,10,10, 0,1, 1255},
    {23, 10,10, 5, 2,1, 1339},
    {23, 10, 5, 5, 2,1, 1355},
    {24,  5, 5, 5, 2,0,    0}
};

// ---------------- helpers ----------------
__device__ __forceinline__ int codeList(int ch, int* o) {
    if (ch == 10) { o[0]=0; o[1]=1; o[2]=2; o[3]=3; return 4; }
    o[0] = ch; return 1;
}

__device__ void addB(float* shB, const float* w,
                     int state, int e0, int e1, int e2,
                     int xp, int trainable, int k)
{
    int a0[6], a1[6], a2[6];
    int n0 = codeList(e0, a0);
    int n1 = codeList(e1, a1);
    int n2 = codeList(e2, a2);
    if (xp == 0) { a0[n0++] = 4; a1[n1++] = 4; }
    int t = 0;
    for (int i0 = 0; i0 < n0; i0++) { int c0 = a0[i0];
        for (int i1 = 0; i1 < n1; i1++) { int c1 = a1[i1];
            if (c0 != 4 && c1 == 4) continue;
            for (int i2 = 0; i2 < n2; i2++) { int c2 = a2[i2];
                shB[((c0*36 + c1*6 + c2) << 5) + state] = trainable ? w[k + t] : 1.0f;
                t++;
            }
        }
    }
}

// round-to-nearest fp32 -> bf16 bits (low 16)
__device__ __forceinline__ unsigned bf16rn(float v) {
    unsigned b = __float_as_uint(v);
    return (b + 0x7fffu + ((b >> 16) & 1u)) >> 16;
}

// ---------------- fused kernel: 3 steps/iter ----------------
__global__ __launch_bounds__(128, 1)
void hmm_fused(const float* __restrict__ tw,
               const float* __restrict__ ew,
               const float* __restrict__ iw,
               const int* __restrict__ tokens,
               float* __restrict__ out, int rows)
{
    extern __shared__ char dyn[];
    float*  shB   = (float*) (dyn + OFF_B);     // [flat][state(32)]
    float4* sQ2   = (float4*)(dyn + OFF_Q2);    // [f*32+lane]: C_p*B[K2_p][f]
    uint2*  sQ1b  = (uint2*) (dyn + OFF_Q1B);   // [f*32+lane]: bf16x4 of B[J_p][f]
    short*  sFlat = (short*) (dyn + OFF_Q1B);   // ALIAS (consumed before Q1b built)
    short4* sTrip = (short4*)(dyn + OFF_TRIP);  // 4 rows x 684 packed triples
    float*  sA    = (float*) (dyn + OFF_A);
    float*  sI    = (float*) (dyn + OFF_I);
    float*  sRed  = (float*) (dyn + OFF_RED);
    const int tid = threadIdx.x;

    // ---- init ----
    for (int i = tid; i < NF*32; i += 128) shB[i] = ((i & 31) < 25) ? -1e30f : 0.0f;
    for (int i = tid; i < 25*25;  i += 128) sA[i] = -1e30f;
    __syncthreads();

    // ---- B logits ----
    if (tid < 29) {
        const int* d = c_adds[tid];
        addB(shB, ew, d[0], d[1], d[2], d[3], d[4], d[5], d[6]);
    }
    // ---- A logits ----
    if (tid == 32) {
        float w0=tw[0],w1=tw[1],w2=tw[2],w3=tw[3],w4=tw[4];
        float w5=tw[5],w6=tw[6],w7=tw[7],w8=tw[8],w9=tw[9];
        sA[0*25+0]=1.f-w0; sA[0*25+1]=w0;
        sA[1*25+2]=1.f;    sA[2*25+3]=1.f;
        sA[3*25+4]=w1;     sA[6*25+7]=w2;
        sA[4*25+5]=1.f;    sA[7*25+8]=1.f;
        sA[5*25+6]=1.f;    sA[8*25+9]=1.f;
        sA[3*25+14]=w3;    sA[6*25+17]=w4;   sA[9*25+20]=w5;
        sA[9*25+10]=1.f-w5;
        sA[14*25+15]=1.f;  sA[17*25+18]=1.f; sA[20*25+21]=1.f;
        sA[15*25+16]=1.f;  sA[18*25+19]=1.f; sA[21*25+22]=1.f;
        sA[16*25+4]=w6;    sA[19*25+7]=w7;   sA[22*25+10]=w8;
        sA[16*25+14]=1.f-w6; sA[19*25+17]=1.f-w7; sA[22*25+20]=1.f-w8;
        sA[3*25+7]=1.f - w9*w9;
        sA[3*25+10]=1.f - w9*w9*w9;
        sA[6*25+10]=1.f - w9*w9;
        sA[10*25+11]=1.f; sA[11*25+12]=1.f; sA[12*25+13]=1.f;
        sA[13*25+13]=1.f; sA[13*25+23]=1.f;
        sA[23*25+23]=1.f; sA[23*25+24]=1.f; sA[24*25+24]=1.f;
    }
    // ---- I softmax ----
    if (tid == 64) {
        float mx = -1e30f;
        for (int i = 0; i < 9; i++) mx = fmaxf(mx, iw[i]);
        float v[9], sum = 0.f;
        for (int i = 0; i < 9; i++) { v[i] = expf(iw[i]-mx); sum += v[i]; }
        for (int i = 0; i < 9; i++) sI[i] = v[i] / sum;
        for (int i = 9; i < 32; i++) sI[i] = 0.f;
    }

    // ---- per-warp: flat contexts (alias region) + packed triples ----
    const int lane = tid & 31;
    const int wq   = tid >> 5;
    const int row  = blockIdx.x * 4 + wq;
    short*  myFlat = sFlat + wq * TLEN;
    short4* myTrip = sTrip + wq * 684;
    const int* tok = tokens + (size_t)row * TLEN;
    int flat0 = 168, flat1 = 144;
    if (row < rows) {
        int c1 = 4, c2 = 4;
        for (int t0 = 0; t0 < TLEN; t0 += 32) {
            int tcv = tok[t0 + lane];
            int t1v = __shfl_up_sync(FULLMASK, tcv, 1);
            int t2v = __shfl_up_sync(FULLMASK, tcv, 2);
            if (lane == 0) { t1v = c1; t2v = c2; }
            if (lane == 1) { t2v = c1; }
            myFlat[t0 + lane] = (short)(t2v*36 + t1v*6 + tcv);
            c2 = __shfl_sync(FULLMASK, tcv, 30);
            c1 = __shfl_sync(FULLMASK, tcv, 31);
        }
        __syncwarp();
        for (int i = lane; i < NTRIP; i += 32) {
            int b = 2 + 3*i;
            myTrip[i] = make_short4(myFlat[b], myFlat[b+1], myFlat[b+2], 0);
        }
        flat0 = myFlat[0];     // save before Q1b overwrites the alias region
        flat1 = myFlat[1];
    }
    __syncthreads();

    // ---- A row softmax ----
    if (tid < 25) {
        float mx = -1e30f;
        for (int j = 0; j < 25; j++) mx = fmaxf(mx, sA[tid*25+j]);
        float s = 0.f;
        for (int j = 0; j < 25; j++) { float v = expf(sA[tid*25+j]-mx); sA[tid*25+j]=v; s+=v; }
        float inv = 1.f / s;
        for (int j = 0; j < 25; j++) sA[tid*25+j] *= inv;
    }
    // ---- B column softmax, 4-way parallel per state ----
    {
        const int s  = tid & 31;
        const int ch = tid >> 5;
        const int f0 = ch * 54, f1 = f0 + 54;
        float mx = -1e30f;
        for (int f = f0; f < f1; f++) mx = fmaxf(mx, shB[(f<<5)+s]);
        sRed[ch*32 + s] = mx;
        __syncthreads();
        mx = fmaxf(fmaxf(sRed[s], sRed[32+s]), fmaxf(sRed[64+s], sRed[96+s]));
        float sum = 0.f;
        for (int f = f0; f < f1; f++) {
            float v = __expf(shB[(f<<5)+s] - mx);
            shB[(f<<5)+s] = v; sum += v;
        }
        __syncthreads();
        sRed[ch*32 + s] = sum;
        __syncthreads();
        float tot = (sRed[s] + sRed[32+s]) + (sRed[64+s] + sRed[96+s]);
        float inv = 1.f / tot;
        for (int f = f0; f < f1; f++) shB[(f<<5)+s] *= inv;
    }
    __syncthreads();

    // ---- 3-step path table for lane j (<=4 paths; 23/24 intermediates pruned:
    //      B[23/24][f] = 0 on every reachable flat -> those paths are exactly 0) ----
    int   ps[4] = {0,0,0,0};
    int   j1[4] = {0,0,0,0};
    int   j2[4] = {0,0,0,0};
    float pcc[4] = {0.f,0.f,0.f,0.f};
    if (lane < 25) {
        int cnt = 0;
        for (int a2 = 0; a2 < c_pcnt[lane]; a2++) {
            int k2 = c_pred[lane][a2];
            if (k2 >= 23) continue;
            for (int a1 = 0; a1 < c_pcnt[k2]; a1++) {
                int k1 = c_pred[k2][a1];
                if (k1 >= 23) continue;
                for (int a0 = 0; a0 < c_pcnt[k1]; a0++) {
                    int s = c_pred[k1][a0];
                    ps[cnt] = s; j1[cnt] = k1; j2[cnt] = k2;
                    pcc[cnt] = sA[s*25+k1] * sA[k1*25+k2] * sA[k2*25+lane] * 8388608.0f; // 2^23
                    cnt++;
                }
            }
        }
    }
    const int S0 = ps[0], S1 = ps[1], S2 = ps[2], S3 = ps[3];

    // ---- build Q2 (float4) and Q1b (bf16x4) tables, stride 32 ----
    {
        int ja0 = j1[0], ja1 = j1[1], ja2 = j1[2], ja3 = j1[3];
        int kb0 = j2[0], kb1 = j2[1], kb2 = j2[2], kb3 = j2[3];
        for (int f = wq * 54; f < wq * 54 + 54; f++) {
            int fo = f << 5;
            float4 q2;
            q2.x = pcc[0] * shB[fo + kb0];
            q2.y = pcc[1] * shB[fo + kb1];
            q2.z = pcc[2] * shB[fo + kb2];
            q2.w = pcc[3] * shB[fo + kb3];
            sQ2[fo + lane] = q2;
            uint2 qb;
            qb.x = bf16rn(shB[fo + ja0]) | (bf16rn(shB[fo + ja1]) << 16);
            qb.y = bf16rn(shB[fo + ja2]) | (bf16rn(shB[fo + ja3]) << 16);
            sQ1b[fo + lane] = qb;
        }
    }
    __syncthreads();

    // 1-step table (t=1)
    const int u0 = c_srcTab[lane*4+0], u1 = c_srcTab[lane*4+1];
    const int u2 = c_srcTab[lane*4+2], u3 = c_srcTab[lane*4+3];
    const int dg = c_deg[lane];
    float v0 = (lane < 25 && dg > 0) ? sA[u0*25 + lane] : 0.f;
    float v1 = (lane < 25 && dg > 1) ? sA[u1*25 + lane] : 0.f;
    float v2 = (lane < 25 && dg > 2) ? sA[u2*25 + lane] : 0.f;
    float v3 = (lane < 25 && dg > 3) ? sA[u3*25 + lane] : 0.f;

    if (row >= rows) return;

    // ---- t = 0 ----
    float a = sI[lane] * shB[(flat0 << 5) + lane];

    // ---- t = 1: single 1-step ----
    {
        float e = shB[(flat1 << 5) + lane];
        float x0 = __shfl_sync(FULLMASK, a, u0);
        float x1 = __shfl_sync(FULLMASK, a, u1);
        float x2 = __shfl_sync(FULLMASK, a, u2);
        float x3 = __shfl_sync(FULLMASK, a, u3);
        a = (fmaf(x0, v0, x1*v1) + fmaf(x2, v2, x3*v3)) * e;
    }
    int expsum = 0;
    float sc = 1.f; int pend = 0;

    // ---- triple step macro: w_p = bf16(B[J_p][f0]) * (C_p*B[K2_p][f1]) * B[j][f2] ----
#define TRIPM(I, MODE)                                                        \
    {                                                                         \
        short4 tf = myTrip[(I)];                                              \
        uint2  qb = sQ1b[(((int)tf.x) << 5) + lane];                          \
        float4 q2 = sQ2 [(((int)tf.y) << 5) + lane];                          \
        float  e  = shB [(((int)tf.z) << 5) + lane];                          \
        float w0 = __uint_as_float(qb.x << 16)        * q2.x * e;             \
        float w1 = __uint_as_float(qb.x & 0xffff0000u) * q2.y * e;            \
        float w2 = __uint_as_float(qb.y << 16)        * q2.z * e;             \
        float w3 = __uint_as_float(qb.y & 0xffff0000u) * q2.w * e;            \
        float x0 = __shfl_sync(FULLMASK, a, S0);                              \
        float x1 = __shfl_sync(FULLMASK, a, S1);                              \
        float x2 = __shfl_sync(FULLMASK, a, S2);                              \
        float x3 = __shfl_sync(FULLMASK, a, S3);                              \
        a = fmaf(x3, w3, fmaf(x2, w2, fmaf(x1, w1, x0 * w0)));                \
        if ((MODE) == 1) {                                                    \
            int m = __reduce_max_sync(FULLMASK, (__float_as_int(a) >> 23) & 255); \
            sc = __int_as_float((254 - m) << 23);                             \
            pend = m - 127;                                                   \
        }                                                                     \
        if ((MODE) == 2) { a *= sc; expsum += pend; }                         \
    }

    // head: triples 0,1 (measure at 0, apply at 1)
    TRIPM(0, 1) TRIPM(1, 2)

    // ---- main: 85 blocks of 8 triples (iters 2..681), 2-ahead staging ----
#define STAGE(i)                                                              \
    {                                                                         \
        short4 tf = myTrip[ib + (i)];                                         \
        uint2  qb = sQ1b[(((int)tf.x) << 5) + lane];                          \
        float4 q2 = sQ2 [(((int)tf.y) << 5) + lane];                          \
        float  e  = shB [(((int)tf.z) << 5) + lane];                          \
        W[(i)][0] = __uint_as_float(qb.x << 16)         * q2.x * e;           \
        W[(i)][1] = __uint_as_float(qb.x & 0xffff0000u) * q2.y * e;           \
        W[(i)][2] = __uint_as_float(qb.y << 16)         * q2.z * e;           \
        W[(i)][3] = __uint_as_float(qb.y & 0xffff0000u) * q2.w * e;           \
    }

    for (int ib = 2; ib <= 674; ib += 8) {
        float W[8][4];
        STAGE(0) STAGE(1)
        #pragma unroll
        for (int i = 0; i < 8; i++) {
            if (i < 6) STAGE(i+2)
            float x0 = __shfl_sync(FULLMASK, a, S0);
            float x1 = __shfl_sync(FULLMASK, a, S1);
            float x2 = __shfl_sync(FULLMASK, a, S2);
            float x3 = __shfl_sync(FULLMASK, a, S3);
            a = fmaf(x3, W[i][3], fmaf(x2, W[i][2], fmaf(x1, W[i][1], x0 * W[i][0])));
            if (i == 5) {
                int m = __reduce_max_sync(FULLMASK, (__float_as_int(a) >> 23) & 255);
                sc = __int_as_float((254 - m) << 23);
                pend = m - 127;
            }
            if (i == 7) { a *= sc; expsum += pend; }
        }
    }
#undef STAGE
#undef TRIPM

    // ---- final: ll = log(sum alpha) + (expsum - 23*682) * ln2 ----
    float s = a;
    #pragma unroll
    for (int o = 16; o; o >>= 1) s += __shfl_xor_sync(FULLMASK, s, o);
    if (lane == 0)
        out[row] = logf(s) + 0.6931471805599453f * (float)(expsum - 15686);
}

// ---------------- entry point ----------------
extern "C" void kernel_launch(void* const* d_in, const int* in_sizes, int n_in,
                              void* d_out, int out_size)
{
    const float* tw     = (const float*)d_in[0];
    const float* ew     = (const float*)d_in[1];
    const float* iw     = (const float*)d_in[2];
    const int*   tokens = (const int*)  d_in[3];
    float*       out    = (float*)d_out;

    int rows = in_sizes[3] / TLEN;

    cudaFuncSetAttribute(hmm_fused,
                         cudaFuncAttributeMaxDynamicSharedMemorySize,
                         SMEM_TOTAL);
    hmm_fused<<<(rows + 3) / 4, 128, SMEM_TOTAL>>>(tw, ew, iw, tokens, out, rows);
}